// round 2
// baseline (speedup 1.0000x reference)
#include <cuda_runtime.h>
#include <math.h>

#define RES   4096
#define DD    128
#define NN    256
#define BB    8
#define SS    256
#define VV    50257
#define LL    2

// Constants matching the reference's fp32 casts of python doubles
#define PHIF   ((float)1.6180339887498948482045868343656381177203)
#define STEPF  ((float)(6.2831853071795864769252867665590 / 4096.0))
#define SCALEF ((float)(4096.0 / 6.2831853071795864769252867665590))

// Scratch (no allocation allowed)
__device__ float g_sin[RES];
__device__ float g_cos[RES];
__device__ float g_X[SS * BB * DD];   // rows m = t*8 + b, 128 cols

// ---------------------------------------------------------------------------
// Kernel 0: build sin/cos tables exactly like the reference (libdevice sinf/cosf)
// ---------------------------------------------------------------------------
__global__ void k_tables() {
    int i = blockIdx.x * blockDim.x + threadIdx.x;
    if (i < RES) {
        float a = __fmul_rn((float)i, STEPF);
        g_sin[i] = sinf(a);
        g_cos[i] = cosf(a);
    }
}

// ---------------------------------------------------------------------------
// Kernel 1: elementwise recurrence over t. One block per b, thread = d.
// emb gathers are independent of h -> prefetch 8 timesteps ahead.
// All recurrence arithmetic uses explicit rn intrinsics (no FMA contraction)
// to match XLA's elementwise lowering bit-for-bit.
// ---------------------------------------------------------------------------
__global__ void k_recur(const int* __restrict__ ids,
                        const float* __restrict__ emb,
                        float* __restrict__ out) {
    __shared__ float s_sin[RES];
    __shared__ float s_cos[RES];
    __shared__ int   s_ids[SS];

    int b = blockIdx.x;
    int d = threadIdx.x;   // 128 threads

    for (int i = d; i < RES; i += 128) { s_sin[i] = g_sin[i]; s_cos[i] = g_cos[i]; }
    for (int i = d; i < SS;  i += 128) s_ids[i] = ids[b * SS + i];
    __syncthreads();

    float hr = 0.0f, hi = 0.0f;

    for (int t0 = 0; t0 < SS; t0 += 8) {
        float wv[8], bv[8];
#pragma unroll
        for (int j = 0; j < 8; ++j) {
            const float* e = emb + (size_t)s_ids[t0 + j] * (2 * DD);
            wv[j] = e[d];
            bv[j] = e[DD + d];
        }
#pragma unroll
        for (int j = 0; j < 8; ++j) {
            int   t     = t0 + j;
            float tphi  = __fmul_rn((float)t, PHIF);
            float num   = __fadd_rn(hr, hi);
            float den   = __fadd_rn(1.0f, fabsf(wv[j]));
            float theta = __fadd_rn(__fadd_rn(__fdiv_rn(num, den), bv[j]), tphi);
            int   idx   = __float2int_rn(__fmul_rn(theta, SCALEF)) & (RES - 1);
            hi = s_sin[idx];
            hr = s_cos[idx];
            g_X[(size_t)t * (BB * DD) + b * DD + d] = __fadd_rn(hr, hi);
        }
    }

    size_t base = (size_t)BB * SS * VV;
    out[base + b * DD + d]            = hr;  // h_real
    out[base + BB * DD + b * DD + d]  = hi;  // h_imag
}

// ---------------------------------------------------------------------------
// Kernel 2: the two MLP layers, one block per timestep t (256 blocks x 256 thr).
// Phase A: thread n computes th[b][n] for all 8 b (K=128 dot, x in smem).
// Phase B: (b,d) pairs, smem-tiled Wr/Wi (32-n chunks, pad 36 for conflict-free
//          float4 LDS).
// ---------------------------------------------------------------------------
__global__ void k_layers(const float* __restrict__ W,
                         const float* __restrict__ bias,
                         const float* __restrict__ Wr,
                         const float* __restrict__ Wi) {
    extern __shared__ float sm[];
    float* s_sin = sm;                  // 4096
    float* s_cos = s_sin + RES;         // 4096
    float* s_x   = s_cos + RES;         // 1024  (8 x 128)
    float* s_cs  = s_x + BB * DD;       // 2048  (8 x 256)
    float* s_sn  = s_cs + BB * NN;      // 2048
    float* s_wr  = s_sn + BB * NN;      // 128*36
    float* s_wi  = s_wr + DD * 36;      // 128*36

    int tid = threadIdx.x;
    int t   = blockIdx.x;

    for (int i = tid; i < RES; i += 256) { s_sin[i] = g_sin[i]; s_cos[i] = g_cos[i]; }
    float* gx = g_X + (size_t)t * (BB * DD);
    for (int i = tid; i < BB * DD; i += 256) s_x[i] = gx[i];
    __syncthreads();

    float tphi = __fmul_rn((float)t, PHIF);
    int n    = tid;
    int dcol = tid & 127;
    int bhi  = tid >> 7;   // 0 or 1

    for (int layer = 0; layer < LL; ++layer) {
        // ---- Phase A: th = x @ W^T + b + tphi, lookups -> s_cs/s_sn
        const float4* Wn = (const float4*)(W + ((size_t)layer * NN + n) * DD);
        const float4* x4 = (const float4*)s_x;
        float acc[8];
#pragma unroll
        for (int bb = 0; bb < 8; ++bb) acc[bb] = 0.0f;
#pragma unroll 8
        for (int q = 0; q < 32; ++q) {
            float4 w = Wn[q];
#pragma unroll
            for (int bb = 0; bb < 8; ++bb) {
                float4 xv = x4[bb * 32 + q];
                acc[bb] += w.x * xv.x + w.y * xv.y + w.z * xv.z + w.w * xv.w;
            }
        }
        float bsn = bias[layer * NN + n];
#pragma unroll
        for (int bb = 0; bb < 8; ++bb) {
            float th  = acc[bb] + bsn + tphi;
            int   idx = __float2int_rn(__fmul_rn(th, SCALEF)) & (RES - 1);
            s_sn[bb * NN + n] = s_sin[idx];
            s_cs[bb * NN + n] = s_cos[idx];
        }
        __syncthreads();

        // ---- Phase B: o[b][d] = cs @ Wr^T + sn @ Wi^T (tile over n)
        float o[4] = {0.0f, 0.0f, 0.0f, 0.0f};
        const float* WrL = Wr + (size_t)layer * DD * NN;
        const float* WiL = Wi + (size_t)layer * DD * NN;
        for (int n0 = 0; n0 < NN; n0 += 32) {
#pragma unroll
            for (int l2 = 0; l2 < 16; ++l2) {
                int f  = tid + 256 * l2;   // 0..4095
                int dd = f >> 5, nn2 = f & 31;
                s_wr[dd * 36 + nn2] = WrL[dd * NN + n0 + nn2];
                s_wi[dd * 36 + nn2] = WiL[dd * NN + n0 + nn2];
            }
            __syncthreads();
            const float4* wr4 = (const float4*)(s_wr + dcol * 36);
            const float4* wi4 = (const float4*)(s_wi + dcol * 36);
#pragma unroll
            for (int q = 0; q < 8; ++q) {
                float4 wr = wr4[q];
                float4 wi = wi4[q];
#pragma unroll
                for (int p = 0; p < 4; ++p) {
                    int bb = bhi + 2 * p;
                    float4 cs = ((const float4*)(s_cs + bb * NN + n0))[q];
                    float4 sn = ((const float4*)(s_sn + bb * NN + n0))[q];
                    o[p] += cs.x * wr.x + cs.y * wr.y + cs.z * wr.z + cs.w * wr.w
                          + sn.x * wi.x + sn.y * wi.y + sn.z * wi.z + sn.w * wi.w;
                }
            }
            __syncthreads();
        }
        // silu + x update
#pragma unroll
        for (int p = 0; p < 4; ++p) {
            int bb = bhi + 2 * p;
            float ov = o[p];
            float sv = ov / (1.0f + expf(-ov));   // o * sigmoid(o)
            s_x[bb * DD + dcol] += sv;
        }
        __syncthreads();
    }

    for (int i = tid; i < BB * DD; i += 256) gx[i] = s_x[i];
}

// ---------------------------------------------------------------------------
// Kernel 3: logits = X(2048x128) @ out_w^T(128x50257), fp32 SIMT.
// 128x128 block tile, full K=128 resident in smem (pitch 132 for alignment +
// conflict-free float4 LDS), 8x8 microtile per thread, 256 threads.
// Stores directly into the (B,S,V) output layout.
// ---------------------------------------------------------------------------
__global__ void k_logits(const float* __restrict__ Wv,
                         float* __restrict__ out) {
    extern __shared__ float sm[];
    float* As = sm;                 // 128 x 132
    float* Bs = sm + 128 * 132;     // 128 x 132

    int tid = threadIdx.x;
    int v0  = blockIdx.x * 128;
    int m0  = blockIdx.y * 128;

    const float4* X4 = (const float4*)g_X;
    const float4* W4 = (const float4*)Wv;
#pragma unroll
    for (int l = 0; l < 16; ++l) {
        int f  = tid + 256 * l;       // float4 index 0..4095
        int m  = f >> 5;
        int kq = f & 31;
        float4 vA = X4[(size_t)(m0 + m) * 32 + kq];
        *(float4*)(As + m * 132 + kq * 4) = vA;
        int vv = v0 + m;
        float4 vB;
        if (vv < VV) vB = W4[(size_t)vv * 32 + kq];
        else         vB = make_float4(0.0f, 0.0f, 0.0f, 0.0f);
        *(float4*)(Bs + m * 132 + kq * 4) = vB;
    }
    __syncthreads();

    int tx = tid & 15;
    int ty = tid >> 4;

    float acc[8][8];
#pragma unroll
    for (int i = 0; i < 8; ++i)
#pragma unroll
        for (int j = 0; j < 8; ++j) acc[i][j] = 0.0f;

#pragma unroll 4
    for (int kq = 0; kq < 32; ++kq) {
        float4 a4[8], b4[8];
#pragma unroll
        for (int i = 0; i < 8; ++i)
            a4[i] = *(const float4*)(As + (ty + 16 * i) * 132 + kq * 4);
#pragma unroll
        for (int j = 0; j < 8; ++j)
            b4[j] = *(const float4*)(Bs + (tx + 16 * j) * 132 + kq * 4);
#pragma unroll
        for (int i = 0; i < 8; ++i)
#pragma unroll
            for (int j = 0; j < 8; ++j) {
                acc[i][j] += a4[i].x * b4[j].x + a4[i].y * b4[j].y
                           + a4[i].z * b4[j].z + a4[i].w * b4[j].w;
            }
    }

#pragma unroll
    for (int i = 0; i < 8; ++i) {
        int m  = m0 + ty + 16 * i;
        int bb = m & 7;
        int tt = m >> 3;
        float* orow = out + (size_t)bb * SS * VV + (size_t)tt * VV;
#pragma unroll
        for (int j = 0; j < 8; ++j) {
            int v = v0 + tx + 16 * j;
            if (v < VV) orow[v] = acc[i][j];
        }
    }
}

// ---------------------------------------------------------------------------
extern "C" void kernel_launch(void* const* d_in, const int* in_sizes, int n_in,
                              void* d_out, int out_size) {
    const int*   input_ids = (const int*)  d_in[0];
    const float* emb       = (const float*)d_in[1];
    const float* layer_W   = (const float*)d_in[2];
    const float* layer_b   = (const float*)d_in[3];
    const float* layer_Wr  = (const float*)d_in[4];
    const float* layer_Wi  = (const float*)d_in[5];
    const float* out_w     = (const float*)d_in[6];
    float* out = (float*)d_out;

    // Dynamic smem sizes
    const int smem_layers = (2 * RES + BB * DD + 2 * BB * NN + 2 * DD * 36) * sizeof(float);
    const int smem_logits = 2 * 128 * 132 * sizeof(float);
    cudaFuncSetAttribute(k_layers, cudaFuncAttributeMaxDynamicSharedMemorySize, smem_layers);
    cudaFuncSetAttribute(k_logits, cudaFuncAttributeMaxDynamicSharedMemorySize, smem_logits);

    k_tables<<<(RES + 255) / 256, 256>>>();
    k_recur<<<BB, DD>>>(input_ids, emb, out);
    k_layers<<<SS, 256, smem_layers>>>(layer_W, layer_b, layer_Wr, layer_Wi);

    dim3 grid((VV + 127) / 128, (SS * BB) / 128);
    k_logits<<<grid, 256, smem_logits>>>(out_w, out);
}

// round 4
// speedup vs baseline: 1.3554x; 1.3554x over previous
#include <cuda_runtime.h>
#include <cuda_bf16.h>
#include <math.h>
#include <stdint.h>

#define RES   4096
#define DD    128
#define NN    256
#define BB    8
#define SS    256
#define VV    50257
#define LL    2

// Constants matching the reference's fp32 casts of python doubles
#define PHIF   ((float)1.6180339887498948482045868343656381177203)
#define STEPF  ((float)(6.2831853071795864769252867665590 / 4096.0))
#define SCALEF ((float)(4096.0 / 6.2831853071795864769252867665590))

// Scratch (no allocation allowed)
__device__ float g_sin[RES];
__device__ float g_cos[RES];
__device__ float g_X[SS * BB * DD];   // rows m = t*8 + b, 128 cols

// ===========================================================================
// Helpers
// ===========================================================================
__device__ __forceinline__ uint32_t smem_u32(const void* p) {
    uint32_t a;
    asm("{ .reg .u64 t; cvta.to.shared.u64 t, %1; cvt.u32.u64 %0, t; }"
        : "=r"(a) : "l"(p));
    return a;
}

__device__ __forceinline__ uint32_t pk(__nv_bfloat16 a, __nv_bfloat16 b) {
    uint16_t ua = *(uint16_t*)&a, ub = *(uint16_t*)&b;
    return (uint32_t)ua | ((uint32_t)ub << 16);
}

// Split fp32 float4 into bf16 hi/lo and store into swizzled smem planes.
// Plane layout: row r (0..127) is 256B; 16B units; unit u at ((u ^ (r&7))<<4).
__device__ __forceinline__ void store_hl2(char* smem, uint32_t offH, uint32_t offL,
                                          int r, int kq, float4 v) {
    __nv_bfloat16 h0 = __float2bfloat16(v.x);
    __nv_bfloat16 h1 = __float2bfloat16(v.y);
    __nv_bfloat16 h2 = __float2bfloat16(v.z);
    __nv_bfloat16 h3 = __float2bfloat16(v.w);
    __nv_bfloat16 l0 = __float2bfloat16(v.x - __bfloat162float(h0));
    __nv_bfloat16 l1 = __float2bfloat16(v.y - __bfloat162float(h1));
    __nv_bfloat16 l2 = __float2bfloat16(v.z - __bfloat162float(h2));
    __nv_bfloat16 l3 = __float2bfloat16(v.w - __bfloat162float(h3));
    uint32_t off = (uint32_t)(r * 256 + (((kq >> 1) ^ (r & 7)) << 4) + (kq & 1) * 8);
    uint2 hp, lp;
    hp.x = pk(h0, h1); hp.y = pk(h2, h3);
    lp.x = pk(l0, l1); lp.y = pk(l2, l3);
    *(uint2*)(smem + offH + off) = hp;
    *(uint2*)(smem + offL + off) = lp;
}

#define LDMATRIX_X4(r0, r1, r2, r3, addr)                                     \
    asm volatile("ldmatrix.sync.aligned.m8n8.x4.shared.b16 {%0,%1,%2,%3}, [%4];" \
        : "=r"(r0), "=r"(r1), "=r"(r2), "=r"(r3) : "r"(addr))

#define MMA_BF16(c, a, b0, b1)                                                \
    asm volatile("mma.sync.aligned.m16n8k16.row.col.f32.bf16.bf16.f32 "       \
        "{%0,%1,%2,%3}, {%4,%5,%6,%7}, {%8,%9}, {%0,%1,%2,%3};"               \
        : "+f"((c)[0]), "+f"((c)[1]), "+f"((c)[2]), "+f"((c)[3])              \
        : "r"((a)[0]), "r"((a)[1]), "r"((a)[2]), "r"((a)[3]),                 \
          "r"(b0), "r"(b1))

// ---------------------------------------------------------------------------
// Kernel 0: build sin/cos tables exactly like the reference
// ---------------------------------------------------------------------------
__global__ void k_tables() {
    int i = blockIdx.x * blockDim.x + threadIdx.x;
    if (i < RES) {
        float a = __fmul_rn((float)i, STEPF);
        g_sin[i] = sinf(a);
        g_cos[i] = cosf(a);
    }
}

// ---------------------------------------------------------------------------
// Kernel 1: elementwise recurrence over t (bit-exact path, unchanged)
// ---------------------------------------------------------------------------
__global__ void k_recur(const int* __restrict__ ids,
                        const float* __restrict__ emb,
                        float* __restrict__ out) {
    __shared__ float s_sin[RES];
    __shared__ float s_cos[RES];
    __shared__ int   s_ids[SS];

    int b = blockIdx.x;
    int d = threadIdx.x;   // 128 threads

    for (int i = d; i < RES; i += 128) { s_sin[i] = g_sin[i]; s_cos[i] = g_cos[i]; }
    for (int i = d; i < SS;  i += 128) s_ids[i] = ids[b * SS + i];
    __syncthreads();

    float hr = 0.0f, hi = 0.0f;

    for (int t0 = 0; t0 < SS; t0 += 8) {
        float wv[8], bv[8];
#pragma unroll
        for (int j = 0; j < 8; ++j) {
            const float* e = emb + (size_t)s_ids[t0 + j] * (2 * DD);
            wv[j] = e[d];
            bv[j] = e[DD + d];
        }
#pragma unroll
        for (int j = 0; j < 8; ++j) {
            int   t     = t0 + j;
            float tphi  = __fmul_rn((float)t, PHIF);
            float num   = __fadd_rn(hr, hi);
            float den   = __fadd_rn(1.0f, fabsf(wv[j]));
            float theta = __fadd_rn(__fadd_rn(__fdiv_rn(num, den), bv[j]), tphi);
            int   idx   = __float2int_rn(__fmul_rn(theta, SCALEF)) & (RES - 1);
            hi = s_sin[idx];
            hr = s_cos[idx];
            g_X[(size_t)t * (BB * DD) + b * DD + d] = __fadd_rn(hr, hi);
        }
    }

    size_t base = (size_t)BB * SS * VV;
    out[base + b * DD + d]            = hr;  // h_real
    out[base + BB * DD + b * DD + d]  = hi;  // h_imag
}

// ---------------------------------------------------------------------------
// Kernel 2: the two MLP layers (unchanged)
// ---------------------------------------------------------------------------
__global__ void k_layers(const float* __restrict__ W,
                         const float* __restrict__ bias,
                         const float* __restrict__ Wr,
                         const float* __restrict__ Wi) {
    extern __shared__ float sm[];
    float* s_sin = sm;                  // 4096
    float* s_cos = s_sin + RES;         // 4096
    float* s_x   = s_cos + RES;         // 1024  (8 x 128)
    float* s_cs  = s_x + BB * DD;       // 2048  (8 x 256)
    float* s_sn  = s_cs + BB * NN;      // 2048
    float* s_wr  = s_sn + BB * NN;      // 128*36
    float* s_wi  = s_wr + DD * 36;      // 128*36

    int tid = threadIdx.x;
    int t   = blockIdx.x;

    for (int i = tid; i < RES; i += 256) { s_sin[i] = g_sin[i]; s_cos[i] = g_cos[i]; }
    float* gx = g_X + (size_t)t * (BB * DD);
    for (int i = tid; i < BB * DD; i += 256) s_x[i] = gx[i];
    __syncthreads();

    float tphi = __fmul_rn((float)t, PHIF);
    int n    = tid;
    int dcol = tid & 127;
    int bhi  = tid >> 7;   // 0 or 1

    for (int layer = 0; layer < LL; ++layer) {
        const float4* Wn = (const float4*)(W + ((size_t)layer * NN + n) * DD);
        const float4* x4 = (const float4*)s_x;
        float acc[8];
#pragma unroll
        for (int bb = 0; bb < 8; ++bb) acc[bb] = 0.0f;
#pragma unroll 8
        for (int q = 0; q < 32; ++q) {
            float4 w = Wn[q];
#pragma unroll
            for (int bb = 0; bb < 8; ++bb) {
                float4 xv = x4[bb * 32 + q];
                acc[bb] += w.x * xv.x + w.y * xv.y + w.z * xv.z + w.w * xv.w;
            }
        }
        float bsn = bias[layer * NN + n];
#pragma unroll
        for (int bb = 0; bb < 8; ++bb) {
            float th  = acc[bb] + bsn + tphi;
            int   idx = __float2int_rn(__fmul_rn(th, SCALEF)) & (RES - 1);
            s_sn[bb * NN + n] = s_sin[idx];
            s_cs[bb * NN + n] = s_cos[idx];
        }
        __syncthreads();

        float o[4] = {0.0f, 0.0f, 0.0f, 0.0f};
        const float* WrL = Wr + (size_t)layer * DD * NN;
        const float* WiL = Wi + (size_t)layer * DD * NN;
        for (int n0 = 0; n0 < NN; n0 += 32) {
#pragma unroll
            for (int l2 = 0; l2 < 16; ++l2) {
                int f  = tid + 256 * l2;   // 0..4095
                int dd = f >> 5, nn2 = f & 31;
                s_wr[dd * 36 + nn2] = WrL[dd * NN + n0 + nn2];
                s_wi[dd * 36 + nn2] = WiL[dd * NN + n0 + nn2];
            }
            __syncthreads();
            const float4* wr4 = (const float4*)(s_wr + dcol * 36);
            const float4* wi4 = (const float4*)(s_wi + dcol * 36);
#pragma unroll
            for (int q = 0; q < 8; ++q) {
                float4 wr = wr4[q];
                float4 wi = wi4[q];
#pragma unroll
                for (int p = 0; p < 4; ++p) {
                    int bb = bhi + 2 * p;
                    float4 cs = ((const float4*)(s_cs + bb * NN + n0))[q];
                    float4 sn = ((const float4*)(s_sn + bb * NN + n0))[q];
                    o[p] += cs.x * wr.x + cs.y * wr.y + cs.z * wr.z + cs.w * wr.w
                          + sn.x * wi.x + sn.y * wi.y + sn.z * wi.z + sn.w * wi.w;
                }
            }
            __syncthreads();
        }
#pragma unroll
        for (int p = 0; p < 4; ++p) {
            int bb = bhi + 2 * p;
            float ov = o[p];
            float sv = ov / (1.0f + expf(-ov));   // o * sigmoid(o)
            s_x[bb * DD + dcol] += sv;
        }
        __syncthreads();
    }

    for (int i = tid; i < BB * DD; i += 256) gx[i] = s_x[i];
}

// ---------------------------------------------------------------------------
// Kernel 3: logits = X(2048x128) @ out_w^T(128x50257) via warp-level bf16
// HMMA (mma.sync m16n8k16), fp32 emulated with 3 terms AhBh + AhBl + AlBh.
// CTA: 128x128 output tile, K=128 resident as bf16 hi/lo planes (128KB smem).
// 8 warps = 2(M) x 4(N); warp tile 64x32.
// ---------------------------------------------------------------------------
#define AH_OFF 0u
#define AL_OFF 32768u
#define BH_OFF 65536u
#define BL_OFF 98304u
#define SMEM_TC 131072u

__global__ void __launch_bounds__(256, 1)
k_logits_mma(const float* __restrict__ Wv, float* __restrict__ out) {
    extern __shared__ char smc[];
    uint32_t sb = smem_u32(smc);

    int tid  = threadIdx.x;
    int lane = tid & 31;
    int wid  = tid >> 5;
    int n0   = blockIdx.x * 128;
    int m0   = blockIdx.y * 128;

    // ---- load + fp32->bf16 hi/lo split into swizzled smem ----
    {
        const float4* X4 = (const float4*)g_X;
        const float4* W4 = (const float4*)Wv;
#pragma unroll 4
        for (int i = 0; i < 16; ++i) {
            int f = tid + 256 * i;      // 0..4095
            int r = f >> 5, kq = f & 31;
            float4 va = X4[(size_t)(m0 + r) * 32 + kq];
            store_hl2(smc, AH_OFF, AL_OFF, r, kq, va);
            float4 vb;
            if (n0 + r < VV) vb = W4[(size_t)(n0 + r) * 32 + kq];
            else             vb = make_float4(0.f, 0.f, 0.f, 0.f);
            store_hl2(smc, BH_OFF, BL_OFF, r, kq, vb);
        }
    }
    __syncthreads();

    int wm = wid & 1;        // 0..1 -> M offset 0/64
    int wn = wid >> 1;       // 0..3 -> N offset 0/32/64/96
    int g  = lane >> 3;      // ldmatrix lane group
    int l7 = lane & 7;

    // ldmatrix lane address components (row&7 == l7 in all cases)
    int ra = l7 + (g & 1) * 8;       // A: row add within m16, unit add g>>1
    int ua = g >> 1;
    int rb = l7 + (g >> 1) * 8;      // B: row add within n16, unit add g&1
    int ub = g & 1;

    uint32_t arow[4], brow[2];
#pragma unroll
    for (int mf = 0; mf < 4; ++mf)
        arow[mf] = sb + (uint32_t)((wm * 64 + mf * 16 + ra) * 256);
#pragma unroll
    for (int nf2 = 0; nf2 < 2; ++nf2)
        brow[nf2] = sb + (uint32_t)((wn * 32 + nf2 * 16 + rb) * 256);

    float acc[4][4][4];
#pragma unroll
    for (int i = 0; i < 4; ++i)
#pragma unroll
        for (int j = 0; j < 4; ++j)
#pragma unroll
            for (int q = 0; q < 4; ++q) acc[i][j][q] = 0.0f;

    const uint32_t abase[3] = { AH_OFF, AH_OFF, AL_OFF };
    const uint32_t bbase[3] = { BH_OFF, BL_OFF, BH_OFF };

#pragma unroll
    for (int p = 0; p < 3; ++p) {
        uint32_t ab = abase[p], bb2 = bbase[p];
#pragma unroll
        for (int k16 = 0; k16 < 8; ++k16) {
            uint32_t uxa = (uint32_t)(((2 * k16 + ua) ^ l7) << 4);
            uint32_t uxb = (uint32_t)(((2 * k16 + ub) ^ l7) << 4);
            uint32_t a[4][4];
#pragma unroll
            for (int mf = 0; mf < 4; ++mf)
                LDMATRIX_X4(a[mf][0], a[mf][1], a[mf][2], a[mf][3],
                            arow[mf] + ab + uxa);
            uint32_t b[2][4];
#pragma unroll
            for (int nf2 = 0; nf2 < 2; ++nf2)
                LDMATRIX_X4(b[nf2][0], b[nf2][1], b[nf2][2], b[nf2][3],
                            brow[nf2] + bb2 + uxb);
#pragma unroll
            for (int mf = 0; mf < 4; ++mf)
#pragma unroll
                for (int nf = 0; nf < 4; ++nf)
                    MMA_BF16(acc[mf][nf], a[mf],
                             b[nf >> 1][(nf & 1) * 2], b[nf >> 1][(nf & 1) * 2 + 1]);
        }
    }

    // ---- epilogue: write into (B,S,V) layout ----
    bool full = (n0 + 128 <= VV);
    int cbase = n0 + wn * 32 + (lane & 3) * 2;
#pragma unroll
    for (int mf = 0; mf < 4; ++mf) {
        int rr = m0 + wm * 64 + mf * 16 + (lane >> 2);
#pragma unroll
        for (int half = 0; half < 2; ++half) {
            int m = rr + half * 8;
            float* orow = out + (size_t)(m & 7) * SS * VV + (size_t)(m >> 3) * VV;
#pragma unroll
            for (int nf = 0; nf < 4; ++nf) {
                int c = cbase + nf * 8;
                float v0 = acc[mf][nf][half * 2 + 0];
                float v1 = acc[mf][nf][half * 2 + 1];
                if (full) {
                    orow[c]     = v0;
                    orow[c + 1] = v1;
                } else {
                    if (c < VV)     orow[c]     = v0;
                    if (c + 1 < VV) orow[c + 1] = v1;
                }
            }
        }
    }
}

// ---------------------------------------------------------------------------
extern "C" void kernel_launch(void* const* d_in, const int* in_sizes, int n_in,
                              void* d_out, int out_size) {
    const int*   input_ids = (const int*)  d_in[0];
    const float* emb       = (const float*)d_in[1];
    const float* layer_W   = (const float*)d_in[2];
    const float* layer_b   = (const float*)d_in[3];
    const float* layer_Wr  = (const float*)d_in[4];
    const float* layer_Wi  = (const float*)d_in[5];
    const float* out_w     = (const float*)d_in[6];
    float* out = (float*)d_out;

    const int smem_layers = (2 * RES + BB * DD + 2 * BB * NN + 2 * DD * 36) * sizeof(float);
    cudaFuncSetAttribute(k_layers,     cudaFuncAttributeMaxDynamicSharedMemorySize, smem_layers);
    cudaFuncSetAttribute(k_logits_mma, cudaFuncAttributeMaxDynamicSharedMemorySize, (int)SMEM_TC);

    k_tables<<<(RES + 255) / 256, 256>>>();
    k_recur<<<BB, DD>>>(input_ids, emb, out);
    k_layers<<<SS, 256, smem_layers>>>(layer_W, layer_b, layer_Wr, layer_Wi);

    dim3 grid((VV + 127) / 128, (SS * BB) / 128);   // 393 x 16
    k_logits_mma<<<grid, 256, SMEM_TC>>>(out_w, out);
}

// round 7
// speedup vs baseline: 1.4757x; 1.0887x over previous
#include <cuda_runtime.h>
#include <cuda_bf16.h>
#include <math.h>
#include <stdint.h>

#define RES   4096
#define DD    128
#define NN    256
#define BB    8
#define SS    256
#define VV    50257
#define LL    2

// Constants matching the reference's fp32 casts of python doubles
#define PHIF   ((float)1.6180339887498948482045868343656381177203)
#define STEPF  ((float)(6.2831853071795864769252867665590 / 4096.0))
#define SCALEF ((float)(4096.0 / 6.2831853071795864769252867665590))

// Scratch (no allocation allowed)
__device__ float g_sin[RES];
__device__ float g_cos[RES];
__device__ float g_X[SS * BB * DD];   // rows m = t*8 + b, 128 cols

// ===========================================================================
// Helpers
// ===========================================================================
__device__ __forceinline__ uint32_t smem_u32(const void* p) {
    uint32_t a;
    asm("{ .reg .u64 t; cvta.to.shared.u64 t, %1; cvt.u32.u64 %0, t; }"
        : "=r"(a) : "l"(p));
    return a;
}

__device__ __forceinline__ uint32_t pk(__nv_bfloat16 a, __nv_bfloat16 b) {
    uint16_t ua = *(uint16_t*)&a, ub = *(uint16_t*)&b;
    return (uint32_t)ua | ((uint32_t)ub << 16);
}

// Split fp32 float4 into bf16 hi/lo and store into swizzled smem planes.
// Plane layout: row r (0..127) is 256B; 16B units; unit u at ((u ^ (r&7))<<4).
__device__ __forceinline__ void store_hl2(char* smem, uint32_t offH, uint32_t offL,
                                          int r, int kq, float4 v) {
    __nv_bfloat16 h0 = __float2bfloat16(v.x);
    __nv_bfloat16 h1 = __float2bfloat16(v.y);
    __nv_bfloat16 h2 = __float2bfloat16(v.z);
    __nv_bfloat16 h3 = __float2bfloat16(v.w);
    __nv_bfloat16 l0 = __float2bfloat16(v.x - __bfloat162float(h0));
    __nv_bfloat16 l1 = __float2bfloat16(v.y - __bfloat162float(h1));
    __nv_bfloat16 l2 = __float2bfloat16(v.z - __bfloat162float(h2));
    __nv_bfloat16 l3 = __float2bfloat16(v.w - __bfloat162float(h3));
    uint32_t off = (uint32_t)(r * 256 + (((kq >> 1) ^ (r & 7)) << 4) + (kq & 1) * 8);
    uint2 hp, lp;
    hp.x = pk(h0, h1); hp.y = pk(h2, h3);
    lp.x = pk(l0, l1); lp.y = pk(l2, l3);
    *(uint2*)(smem + offH + off) = hp;
    *(uint2*)(smem + offL + off) = lp;
}

#define LDMATRIX_X4(r0, r1, r2, r3, addr)                                     \
    asm volatile("ldmatrix.sync.aligned.m8n8.x4.shared.b16 {%0,%1,%2,%3}, [%4];" \
        : "=r"(r0), "=r"(r1), "=r"(r2), "=r"(r3) : "r"(addr))

#define MMA_BF16(c, a0, a1, a2, a3, b0, b1)                                   \
    asm volatile("mma.sync.aligned.m16n8k16.row.col.f32.bf16.bf16.f32 "       \
        "{%0,%1,%2,%3}, {%4,%5,%6,%7}, {%8,%9}, {%0,%1,%2,%3};"               \
        : "+f"((c)[0]), "+f"((c)[1]), "+f"((c)[2]), "+f"((c)[3])              \
        : "r"(a0), "r"(a1), "r"(a2), "r"(a3), "r"(b0), "r"(b1))

// ---------------------------------------------------------------------------
// Kernel 0: build sin/cos tables exactly like the reference
// ---------------------------------------------------------------------------
__global__ void k_tables() {
    int i = blockIdx.x * blockDim.x + threadIdx.x;
    if (i < RES) {
        float a = __fmul_rn((float)i, STEPF);
        g_sin[i] = sinf(a);
        g_cos[i] = cosf(a);
    }
}

// ---------------------------------------------------------------------------
// Kernel 1: elementwise recurrence over t (bit-exact path, unchanged)
// ---------------------------------------------------------------------------
__global__ void k_recur(const int* __restrict__ ids,
                        const float* __restrict__ emb,
                        float* __restrict__ out) {
    __shared__ float s_sin[RES];
    __shared__ float s_cos[RES];
    __shared__ int   s_ids[SS];

    int b = blockIdx.x;
    int d = threadIdx.x;   // 128 threads

    for (int i = d; i < RES; i += 128) { s_sin[i] = g_sin[i]; s_cos[i] = g_cos[i]; }
    for (int i = d; i < SS;  i += 128) s_ids[i] = ids[b * SS + i];
    __syncthreads();

    float hr = 0.0f, hi = 0.0f;

    for (int t0 = 0; t0 < SS; t0 += 8) {
        float wv[8], bv[8];
#pragma unroll
        for (int j = 0; j < 8; ++j) {
            const float* e = emb + (size_t)s_ids[t0 + j] * (2 * DD);
            wv[j] = e[d];
            bv[j] = e[DD + d];
        }
#pragma unroll
        for (int j = 0; j < 8; ++j) {
            int   t     = t0 + j;
            float tphi  = __fmul_rn((float)t, PHIF);
            float num   = __fadd_rn(hr, hi);
            float den   = __fadd_rn(1.0f, fabsf(wv[j]));
            float theta = __fadd_rn(__fadd_rn(__fdiv_rn(num, den), bv[j]), tphi);
            int   idx   = __float2int_rn(__fmul_rn(theta, SCALEF)) & (RES - 1);
            hi = s_sin[idx];
            hr = s_cos[idx];
            g_X[(size_t)t * (BB * DD) + b * DD + d] = __fadd_rn(hr, hi);
        }
    }

    size_t base = (size_t)BB * SS * VV;
    out[base + b * DD + d]            = hr;  // h_real
    out[base + BB * DD + b * DD + d]  = hi;  // h_imag
}

// ---------------------------------------------------------------------------
// Kernel 2: the two MLP layers (unchanged)
// ---------------------------------------------------------------------------
__global__ void k_layers(const float* __restrict__ W,
                         const float* __restrict__ bias,
                         const float* __restrict__ Wr,
                         const float* __restrict__ Wi) {
    extern __shared__ float sm[];
    float* s_sin = sm;                  // 4096
    float* s_cos = s_sin + RES;         // 4096
    float* s_x   = s_cos + RES;         // 1024  (8 x 128)
    float* s_cs  = s_x + BB * DD;       // 2048  (8 x 256)
    float* s_sn  = s_cs + BB * NN;      // 2048
    float* s_wr  = s_sn + BB * NN;      // 128*36
    float* s_wi  = s_wr + DD * 36;      // 128*36

    int tid = threadIdx.x;
    int t   = blockIdx.x;

    for (int i = tid; i < RES; i += 256) { s_sin[i] = g_sin[i]; s_cos[i] = g_cos[i]; }
    float* gx = g_X + (size_t)t * (BB * DD);
    for (int i = tid; i < BB * DD; i += 256) s_x[i] = gx[i];
    __syncthreads();

    float tphi = __fmul_rn((float)t, PHIF);
    int n    = tid;
    int dcol = tid & 127;
    int bhi  = tid >> 7;   // 0 or 1

    for (int layer = 0; layer < LL; ++layer) {
        const float4* Wn = (const float4*)(W + ((size_t)layer * NN + n) * DD);
        const float4* x4 = (const float4*)s_x;
        float acc[8];
#pragma unroll
        for (int bb = 0; bb < 8; ++bb) acc[bb] = 0.0f;
#pragma unroll 8
        for (int q = 0; q < 32; ++q) {
            float4 w = Wn[q];
#pragma unroll
            for (int bb = 0; bb < 8; ++bb) {
                float4 xv = x4[bb * 32 + q];
                acc[bb] += w.x * xv.x + w.y * xv.y + w.z * xv.z + w.w * xv.w;
            }
        }
        float bsn = bias[layer * NN + n];
#pragma unroll
        for (int bb = 0; bb < 8; ++bb) {
            float th  = acc[bb] + bsn + tphi;
            int   idx = __float2int_rn(__fmul_rn(th, SCALEF)) & (RES - 1);
            s_sn[bb * NN + n] = s_sin[idx];
            s_cs[bb * NN + n] = s_cos[idx];
        }
        __syncthreads();

        float o[4] = {0.0f, 0.0f, 0.0f, 0.0f};
        const float* WrL = Wr + (size_t)layer * DD * NN;
        const float* WiL = Wi + (size_t)layer * DD * NN;
        for (int n0 = 0; n0 < NN; n0 += 32) {
#pragma unroll
            for (int l2 = 0; l2 < 16; ++l2) {
                int f  = tid + 256 * l2;   // 0..4095
                int dd = f >> 5, nn2 = f & 31;
                s_wr[dd * 36 + nn2] = WrL[dd * NN + n0 + nn2];
                s_wi[dd * 36 + nn2] = WiL[dd * NN + n0 + nn2];
            }
            __syncthreads();
            const float4* wr4 = (const float4*)(s_wr + dcol * 36);
            const float4* wi4 = (const float4*)(s_wi + dcol * 36);
#pragma unroll
            for (int q = 0; q < 8; ++q) {
                float4 wr = wr4[q];
                float4 wi = wi4[q];
#pragma unroll
                for (int p = 0; p < 4; ++p) {
                    int bb = bhi + 2 * p;
                    float4 cs = ((const float4*)(s_cs + bb * NN + n0))[q];
                    float4 sn = ((const float4*)(s_sn + bb * NN + n0))[q];
                    o[p] += cs.x * wr.x + cs.y * wr.y + cs.z * wr.z + cs.w * wr.w
                          + sn.x * wi.x + sn.y * wi.y + sn.z * wi.z + sn.w * wi.w;
                }
            }
            __syncthreads();
        }
#pragma unroll
        for (int p = 0; p < 4; ++p) {
            int bb = bhi + 2 * p;
            float ov = o[p];
            float sv = ov / (1.0f + expf(-ov));   // o * sigmoid(o)
            s_x[bb * DD + dcol] += sv;
        }
        __syncthreads();
    }

    for (int i = tid; i < BB * DD; i += 256) gx[i] = s_x[i];
}

// ---------------------------------------------------------------------------
// Kernel 3: logits = X(2048x128) @ out_w^T(128x50257) via warp-level bf16
// HMMA, fp32 emulated with 3 terms AhBh + AhBl + AlBh.
// CTA: 128x128 output tile, K=128 resident as bf16 hi/lo planes (128KB smem).
// 16 warps (512 thr) = 4(M) x 4(N); warp tile 32x32; acc = 32 regs/thread.
// Fragment loads ordered for minimal liveness: (aH,bH)->T1, bL->T2, aL->T3.
// ---------------------------------------------------------------------------
#define AH_OFF 0u
#define AL_OFF 32768u
#define BH_OFF 65536u
#define BL_OFF 98304u
#define SMEM_TC 131072u

__global__ void __launch_bounds__(512, 1)
k_logits_mma(const float* __restrict__ Wv, float* __restrict__ out) {
    extern __shared__ char smc[];
    uint32_t sb = smem_u32(smc);

    int tid  = threadIdx.x;
    int lane = tid & 31;
    int wid  = tid >> 5;
    int n0   = blockIdx.x * 128;
    int m0   = blockIdx.y * 128;
    bool full = (blockIdx.x != gridDim.x - 1);   // last N-tile is the ragged one

    // ---- load + fp32->bf16 hi/lo split into swizzled smem ----
    {
        const float4* X4 = (const float4*)g_X;
        const float4* W4 = (const float4*)Wv;
#pragma unroll 4
        for (int i = 0; i < 8; ++i) {
            int f = tid + 512 * i;      // 0..4095
            int r = f >> 5, kq = f & 31;
            float4 va = X4[(size_t)(m0 + r) * 32 + kq];
            store_hl2(smc, AH_OFF, AL_OFF, r, kq, va);
            float4 vb;
            if (full || n0 + r < VV) vb = W4[(size_t)(n0 + r) * 32 + kq];
            else                     vb = make_float4(0.f, 0.f, 0.f, 0.f);
            store_hl2(smc, BH_OFF, BL_OFF, r, kq, vb);
        }
    }
    __syncthreads();

    int wm = wid & 3;        // 0..3 -> M offset 0/32/64/96
    int wn = wid >> 2;       // 0..3 -> N offset 0/32/64/96
    int g  = lane >> 3;      // ldmatrix lane group
    int l7 = lane & 7;

    // ldmatrix lane address components (row low-3 bits == l7 in all cases)
    int ra = l7 + (g & 1) * 8;       // A: row within m16; unit add g>>1
    int ua = g >> 1;
    int rb = l7 + (g >> 1) * 8;      // B: row within n16; unit add g&1
    int ub = g & 1;

    uint32_t arow[2], brow[2];
#pragma unroll
    for (int mf = 0; mf < 2; ++mf)
        arow[mf] = sb + (uint32_t)((wm * 32 + mf * 16 + ra) * 256);
#pragma unroll
    for (int nf2 = 0; nf2 < 2; ++nf2)
        brow[nf2] = sb + (uint32_t)((wn * 32 + nf2 * 16 + rb) * 256);

    float acc[2][4][4];
#pragma unroll
    for (int i = 0; i < 2; ++i)
#pragma unroll
        for (int j = 0; j < 4; ++j)
#pragma unroll
            for (int q = 0; q < 4; ++q) acc[i][j][q] = 0.0f;

#pragma unroll
    for (int k16 = 0; k16 < 8; ++k16) {
        uint32_t uxa = (uint32_t)(((2 * k16 + ua) ^ l7) << 4);
        uint32_t uxb = (uint32_t)(((2 * k16 + ub) ^ l7) << 4);

        uint32_t aH[2][4], bH[2][4];
#pragma unroll
        for (int mf = 0; mf < 2; ++mf)
            LDMATRIX_X4(aH[mf][0], aH[mf][1], aH[mf][2], aH[mf][3],
                        arow[mf] + AH_OFF + uxa);
#pragma unroll
        for (int nf2 = 0; nf2 < 2; ++nf2)
            LDMATRIX_X4(bH[nf2][0], bH[nf2][1], bH[nf2][2], bH[nf2][3],
                        brow[nf2] + BH_OFF + uxb);

        // Term 1: Ah * Bh
#pragma unroll
        for (int mf = 0; mf < 2; ++mf)
#pragma unroll
            for (int nf = 0; nf < 4; ++nf)
                MMA_BF16(acc[mf][nf], aH[mf][0], aH[mf][1], aH[mf][2], aH[mf][3],
                         bH[nf >> 1][(nf & 1) * 2], bH[nf >> 1][(nf & 1) * 2 + 1]);

        // Term 2: Ah * Bl
        {
            uint32_t bL[2][4];
#pragma unroll
            for (int nf2 = 0; nf2 < 2; ++nf2)
                LDMATRIX_X4(bL[nf2][0], bL[nf2][1], bL[nf2][2], bL[nf2][3],
                            brow[nf2] + BL_OFF + uxb);
#pragma unroll
            for (int mf = 0; mf < 2; ++mf)
#pragma unroll
                for (int nf = 0; nf < 4; ++nf)
                    MMA_BF16(acc[mf][nf], aH[mf][0], aH[mf][1], aH[mf][2], aH[mf][3],
                             bL[nf >> 1][(nf & 1) * 2], bL[nf >> 1][(nf & 1) * 2 + 1]);
        }

        // Term 3: Al * Bh
        {
            uint32_t aL[2][4];
#pragma unroll
            for (int mf = 0; mf < 2; ++mf)
                LDMATRIX_X4(aL[mf][0], aL[mf][1], aL[mf][2], aL[mf][3],
                            arow[mf] + AL_OFF + uxa);
#pragma unroll
            for (int mf = 0; mf < 2; ++mf)
#pragma unroll
                for (int nf = 0; nf < 4; ++nf)
                    MMA_BF16(acc[mf][nf], aL[mf][0], aL[mf][1], aL[mf][2], aL[mf][3],
                             bH[nf >> 1][(nf & 1) * 2], bH[nf >> 1][(nf & 1) * 2 + 1]);
        }
    }

    // ---- epilogue: write into (B,S,V) layout ----
    int cbase = n0 + wn * 32 + (lane & 3) * 2;
#pragma unroll
    for (int mf = 0; mf < 2; ++mf) {
        int rr = m0 + wm * 32 + mf * 16 + (lane >> 2);
#pragma unroll
        for (int half = 0; half < 2; ++half) {
            int m = rr + half * 8;
            float* orow = out + (size_t)(m & 7) * SS * VV + (size_t)(m >> 3) * VV;
#pragma unroll
            for (int nf = 0; nf < 4; ++nf) {
                int c = cbase + nf * 8;
                float v0 = acc[mf][nf][half * 2 + 0];
                float v1 = acc[mf][nf][half * 2 + 1];
                if (full) {
                    orow[c]     = v0;
                    orow[c + 1] = v1;
                } else {
                    if (c < VV)     orow[c]     = v0;
                    if (c + 1 < VV) orow[c + 1] = v1;
                }
            }
        }
    }
}

// ---------------------------------------------------------------------------
extern "C" void kernel_launch(void* const* d_in, const int* in_sizes, int n_in,
                              void* d_out, int out_size) {
    const int*   input_ids = (const int*)  d_in[0];
    const float* emb       = (const float*)d_in[1];
    const float* layer_W   = (const float*)d_in[2];
    const float* layer_b   = (const float*)d_in[3];
    const float* layer_Wr  = (const float*)d_in[4];
    const float* layer_Wi  = (const float*)d_in[5];
    const float* out_w     = (const float*)d_in[6];
    float* out = (float*)d_out;

    const int smem_layers = (2 * RES + BB * DD + 2 * BB * NN + 2 * DD * 36) * sizeof(float);
    cudaFuncSetAttribute(k_layers,     cudaFuncAttributeMaxDynamicSharedMemorySize, smem_layers);
    cudaFuncSetAttribute(k_logits_mma, cudaFuncAttributeMaxDynamicSharedMemorySize, (int)SMEM_TC);

    k_tables<<<(RES + 255) / 256, 256>>>();
    k_recur<<<BB, DD>>>(input_ids, emb, out);
    k_layers<<<SS, 256, smem_layers>>>(layer_W, layer_b, layer_Wr, layer_Wi);

    dim3 grid((VV + 127) / 128, (SS * BB) / 128);   // 393 x 16
    k_logits_mma<<<grid, 512, SMEM_TC>>>(out_w, out);
}

// round 8
// speedup vs baseline: 1.7535x; 1.1883x over previous
#include <cuda_runtime.h>
#include <cuda_bf16.h>
#include <math.h>
#include <stdint.h>

#define RES   4096
#define DD    128
#define NN    256
#define BB    8
#define SS    256
#define VV    50257
#define LL    2
#define WROWS 50304          // 393 * 128, padded vocab rows
#define NTILES 393
#define MTILES 16

// Constants matching the reference's fp32 casts of python doubles
#define PHIF   ((float)1.6180339887498948482045868343656381177203)
#define STEPF  ((float)(6.2831853071795864769252867665590 / 4096.0))
#define SCALEF ((float)(4096.0 / 6.2831853071795864769252867665590))

// Scratch (no allocation allowed)
__device__ float g_sin[RES];
__device__ float g_cos[RES];
__device__ float g_X[SS * BB * DD];   // rows m = t*8 + b, 128 cols

// Pre-split bf16 hi/lo planes (row-major: row*128 bf16 = 256B rows)
__device__ __align__(16) __nv_bfloat16 g_Wh[WROWS * DD];
__device__ __align__(16) __nv_bfloat16 g_Wl[WROWS * DD];
__device__ __align__(16) __nv_bfloat16 g_Xh[SS * BB * DD];
__device__ __align__(16) __nv_bfloat16 g_Xl[SS * BB * DD];

// ===========================================================================
// Helpers
// ===========================================================================
__device__ __forceinline__ uint32_t smem_u32(const void* p) {
    uint32_t a;
    asm("{ .reg .u64 t; cvta.to.shared.u64 t, %1; cvt.u32.u64 %0, t; }"
        : "=r"(a) : "l"(p));
    return a;
}

__device__ __forceinline__ uint32_t pk(__nv_bfloat16 a, __nv_bfloat16 b) {
    uint16_t ua = *(uint16_t*)&a, ub = *(uint16_t*)&b;
    return (uint32_t)ua | ((uint32_t)ub << 16);
}

#define LDMATRIX_X4(r0, r1, r2, r3, addr)                                     \
    asm volatile("ldmatrix.sync.aligned.m8n8.x4.shared.b16 {%0,%1,%2,%3}, [%4];" \
        : "=r"(r0), "=r"(r1), "=r"(r2), "=r"(r3) : "r"(addr))

#define MMA_BF16(c, a0, a1, a2, a3, b0, b1)                                   \
    asm volatile("mma.sync.aligned.m16n8k16.row.col.f32.bf16.bf16.f32 "       \
        "{%0,%1,%2,%3}, {%4,%5,%6,%7}, {%8,%9}, {%0,%1,%2,%3};"               \
        : "+f"((c)[0]), "+f"((c)[1]), "+f"((c)[2]), "+f"((c)[3])              \
        : "r"(a0), "r"(a1), "r"(a2), "r"(a3), "r"(b0), "r"(b1))

#define CP_ASYNC16(smaddr, gptr)                                              \
    asm volatile("cp.async.cg.shared.global [%0], [%1], 16;"                  \
        :: "r"(smaddr), "l"(gptr))
#define CP_COMMIT() asm volatile("cp.async.commit_group;" ::: "memory")
#define CP_WAIT0()  asm volatile("cp.async.wait_group 0;" ::: "memory")
#define CP_WAIT1()  asm volatile("cp.async.wait_group 1;" ::: "memory")

// ---------------------------------------------------------------------------
// Kernel 0: build sin/cos tables exactly like the reference
// ---------------------------------------------------------------------------
__global__ void k_tables() {
    int i = blockIdx.x * blockDim.x + threadIdx.x;
    if (i < RES) {
        float a = __fmul_rn((float)i, STEPF);
        g_sin[i] = sinf(a);
        g_cos[i] = cosf(a);
    }
}

// ---------------------------------------------------------------------------
// Kernel 1: elementwise recurrence over t (bit-exact path, unchanged)
// ---------------------------------------------------------------------------
__global__ void k_recur(const int* __restrict__ ids,
                        const float* __restrict__ emb,
                        float* __restrict__ out) {
    __shared__ float s_sin[RES];
    __shared__ float s_cos[RES];
    __shared__ int   s_ids[SS];

    int b = blockIdx.x;
    int d = threadIdx.x;   // 128 threads

    for (int i = d; i < RES; i += 128) { s_sin[i] = g_sin[i]; s_cos[i] = g_cos[i]; }
    for (int i = d; i < SS;  i += 128) s_ids[i] = ids[b * SS + i];
    __syncthreads();

    float hr = 0.0f, hi = 0.0f;

    for (int t0 = 0; t0 < SS; t0 += 8) {
        float wv[8], bv[8];
#pragma unroll
        for (int j = 0; j < 8; ++j) {
            const float* e = emb + (size_t)s_ids[t0 + j] * (2 * DD);
            wv[j] = e[d];
            bv[j] = e[DD + d];
        }
#pragma unroll
        for (int j = 0; j < 8; ++j) {
            int   t     = t0 + j;
            float tphi  = __fmul_rn((float)t, PHIF);
            float num   = __fadd_rn(hr, hi);
            float den   = __fadd_rn(1.0f, fabsf(wv[j]));
            float theta = __fadd_rn(__fadd_rn(__fdiv_rn(num, den), bv[j]), tphi);
            int   idx   = __float2int_rn(__fmul_rn(theta, SCALEF)) & (RES - 1);
            hi = s_sin[idx];
            hr = s_cos[idx];
            g_X[(size_t)t * (BB * DD) + b * DD + d] = __fadd_rn(hr, hi);
        }
    }

    size_t base = (size_t)BB * SS * VV;
    out[base + b * DD + d]            = hr;  // h_real
    out[base + BB * DD + b * DD + d]  = hi;  // h_imag
}

// ---------------------------------------------------------------------------
// Kernel 2: the two MLP layers (unchanged)
// ---------------------------------------------------------------------------
__global__ void k_layers(const float* __restrict__ W,
                         const float* __restrict__ bias,
                         const float* __restrict__ Wr,
                         const float* __restrict__ Wi) {
    extern __shared__ float sm[];
    float* s_sin = sm;                  // 4096
    float* s_cos = s_sin + RES;         // 4096
    float* s_x   = s_cos + RES;         // 1024  (8 x 128)
    float* s_cs  = s_x + BB * DD;       // 2048  (8 x 256)
    float* s_sn  = s_cs + BB * NN;      // 2048
    float* s_wr  = s_sn + BB * NN;      // 128*36
    float* s_wi  = s_wr + DD * 36;      // 128*36

    int tid = threadIdx.x;
    int t   = blockIdx.x;

    for (int i = tid; i < RES; i += 256) { s_sin[i] = g_sin[i]; s_cos[i] = g_cos[i]; }
    float* gx = g_X + (size_t)t * (BB * DD);
    for (int i = tid; i < BB * DD; i += 256) s_x[i] = gx[i];
    __syncthreads();

    float tphi = __fmul_rn((float)t, PHIF);
    int n    = tid;
    int dcol = tid & 127;
    int bhi  = tid >> 7;   // 0 or 1

    for (int layer = 0; layer < LL; ++layer) {
        const float4* Wn = (const float4*)(W + ((size_t)layer * NN + n) * DD);
        const float4* x4 = (const float4*)s_x;
        float acc[8];
#pragma unroll
        for (int bb = 0; bb < 8; ++bb) acc[bb] = 0.0f;
#pragma unroll 8
        for (int q = 0; q < 32; ++q) {
            float4 w = Wn[q];
#pragma unroll
            for (int bb = 0; bb < 8; ++bb) {
                float4 xv = x4[bb * 32 + q];
                acc[bb] += w.x * xv.x + w.y * xv.y + w.z * xv.z + w.w * xv.w;
            }
        }
        float bsn = bias[layer * NN + n];
#pragma unroll
        for (int bb = 0; bb < 8; ++bb) {
            float th  = acc[bb] + bsn + tphi;
            int   idx = __float2int_rn(__fmul_rn(th, SCALEF)) & (RES - 1);
            s_sn[bb * NN + n] = s_sin[idx];
            s_cs[bb * NN + n] = s_cos[idx];
        }
        __syncthreads();

        float o[4] = {0.0f, 0.0f, 0.0f, 0.0f};
        const float* WrL = Wr + (size_t)layer * DD * NN;
        const float* WiL = Wi + (size_t)layer * DD * NN;
        for (int n0 = 0; n0 < NN; n0 += 32) {
#pragma unroll
            for (int l2 = 0; l2 < 16; ++l2) {
                int f  = tid + 256 * l2;   // 0..4095
                int dd = f >> 5, nn2 = f & 31;
                s_wr[dd * 36 + nn2] = WrL[dd * NN + n0 + nn2];
                s_wi[dd * 36 + nn2] = WiL[dd * NN + n0 + nn2];
            }
            __syncthreads();
            const float4* wr4 = (const float4*)(s_wr + dcol * 36);
            const float4* wi4 = (const float4*)(s_wi + dcol * 36);
#pragma unroll
            for (int q = 0; q < 8; ++q) {
                float4 wr = wr4[q];
                float4 wi = wi4[q];
#pragma unroll
                for (int p = 0; p < 4; ++p) {
                    int bb = bhi + 2 * p;
                    float4 cs = ((const float4*)(s_cs + bb * NN + n0))[q];
                    float4 sn = ((const float4*)(s_sn + bb * NN + n0))[q];
                    o[p] += cs.x * wr.x + cs.y * wr.y + cs.z * wr.z + cs.w * wr.w
                          + sn.x * wi.x + sn.y * wi.y + sn.z * wi.z + sn.w * wi.w;
                }
            }
            __syncthreads();
        }
#pragma unroll
        for (int p = 0; p < 4; ++p) {
            int bb = bhi + 2 * p;
            float ov = o[p];
            float sv = ov / (1.0f + expf(-ov));   // o * sigmoid(o)
            s_x[bb * DD + dcol] += sv;
        }
        __syncthreads();
    }

    for (int i = tid; i < BB * DD; i += 256) gx[i] = s_x[i];
}

// ---------------------------------------------------------------------------
// Split kernels: fp32 -> bf16 hi/lo planes, row-major (cp.async-ready).
// ---------------------------------------------------------------------------
__device__ __forceinline__ void split4(float4 v, uint2& hp, uint2& lp) {
    __nv_bfloat16 h0 = __float2bfloat16(v.x);
    __nv_bfloat16 h1 = __float2bfloat16(v.y);
    __nv_bfloat16 h2 = __float2bfloat16(v.z);
    __nv_bfloat16 h3 = __float2bfloat16(v.w);
    __nv_bfloat16 l0 = __float2bfloat16(v.x - __bfloat162float(h0));
    __nv_bfloat16 l1 = __float2bfloat16(v.y - __bfloat162float(h1));
    __nv_bfloat16 l2 = __float2bfloat16(v.z - __bfloat162float(h2));
    __nv_bfloat16 l3 = __float2bfloat16(v.w - __bfloat162float(h3));
    hp = make_uint2(pk(h0, h1), pk(h2, h3));
    lp = make_uint2(pk(l0, l1), pk(l2, l3));
}

__global__ void k_split_w(const float* __restrict__ Wv) {
    int f = blockIdx.x * blockDim.x + threadIdx.x;   // 0 .. WROWS*32-1
    int r = f >> 5, kq = f & 31;
    float4 v = make_float4(0.f, 0.f, 0.f, 0.f);
    if (r < VV) v = ((const float4*)Wv)[(size_t)r * 32 + kq];
    uint2 hp, lp;
    split4(v, hp, lp);
    ((uint2*)g_Wh)[f] = hp;
    ((uint2*)g_Wl)[f] = lp;
}

__global__ void k_split_x() {
    int f = blockIdx.x * blockDim.x + threadIdx.x;   // 0 .. 2048*32-1
    float4 v = ((const float4*)g_X)[f];
    uint2 hp, lp;
    split4(v, hp, lp);
    ((uint2*)g_Xh)[f] = hp;
    ((uint2*)g_Xl)[f] = lp;
}

// ---------------------------------------------------------------------------
// Kernel 3: persistent-N pipelined logits GEMM.
//   grid = 393 N-tiles; each CTA: B planes loaded ONCE (cp.async), then loops
//   16 M-tiles with double-buffered A planes prefetched via cp.async.
//   16 warps = 4(M) x 4(N), warp tile 32x32; 3-term bf16 fp32 emulation.
// smem: BH 32K | BL 32K | A0(H32K,L32K) | A1(H32K,L32K) = 192KB
// ---------------------------------------------------------------------------
#define PB_BH 0u
#define PB_BL 32768u
#define PB_A0 65536u
#define PB_A1 131072u
#define SMEM_PIPE 196608u

__global__ void __launch_bounds__(512, 1)
k_logits_pipe(float* __restrict__ out) {
    extern __shared__ char smc[];
    uint32_t sb = smem_u32(smc);

    int tid  = threadIdx.x;
    int lane = tid & 31;
    int wid  = tid >> 5;
    int n0   = blockIdx.x * 128;
    bool full = (blockIdx.x != gridDim.x - 1);

    const char* gWh = (const char*)g_Wh;
    const char* gWl = (const char*)g_Wl;
    const char* gXh = (const char*)g_Xh;
    const char* gXl = (const char*)g_Xl;

    // ---- issue B planes + A tile 0 (group 0) ----
#pragma unroll
    for (int i = 0; i < 4; ++i) {
        int f = tid + 512 * i;            // 0..2047
        int r = f >> 4, u = f & 15;
        uint32_t so = (uint32_t)(r * 256 + ((u ^ (r & 7)) << 4));
        size_t   go = (size_t)(n0 + r) * 256 + u * 16;
        CP_ASYNC16(sb + PB_BH + so, gWh + go);
        CP_ASYNC16(sb + PB_BL + so, gWl + go);
    }
#pragma unroll
    for (int i = 0; i < 4; ++i) {
        int f = tid + 512 * i;
        int r = f >> 4, u = f & 15;
        uint32_t so = (uint32_t)(r * 256 + ((u ^ (r & 7)) << 4));
        size_t   go = (size_t)r * 256 + u * 16;
        CP_ASYNC16(sb + PB_A0 + so, gXh + go);
        CP_ASYNC16(sb + PB_A0 + 32768u + so, gXl + go);
    }
    CP_COMMIT();

    int wm = wid & 3;        // M offset within tile: 0/32/64/96
    int wn = wid >> 2;       // N offset: 0/32/64/96
    int g  = lane >> 3;
    int l7 = lane & 7;
    int ra = l7 + (g & 1) * 8;
    int ua = g >> 1;
    int rb = l7 + (g >> 1) * 8;
    int ub = g & 1;

    uint32_t arel[2];
#pragma unroll
    for (int mf = 0; mf < 2; ++mf)
        arel[mf] = (uint32_t)((wm * 32 + mf * 16 + ra) * 256);
    uint32_t brow[2];
#pragma unroll
    for (int nf2 = 0; nf2 < 2; ++nf2)
        brow[nf2] = sb + PB_BH + (uint32_t)((wn * 32 + nf2 * 16 + rb) * 256);

    int cbase = n0 + wn * 32 + (lane & 3) * 2;

    for (int mt = 0; mt < MTILES; ++mt) {
        // prefetch next A tile into the other buffer
        if (mt < MTILES - 1) {
            uint32_t ab = (mt & 1) ? PB_A0 : PB_A1;    // buffer (mt+1)&1
#pragma unroll
            for (int i = 0; i < 4; ++i) {
                int f = tid + 512 * i;
                int r = f >> 4, u = f & 15;
                uint32_t so = (uint32_t)(r * 256 + ((u ^ (r & 7)) << 4));
                size_t   go = (size_t)((mt + 1) * 128 + r) * 256 + u * 16;
                CP_ASYNC16(sb + ab + so, gXh + go);
                CP_ASYNC16(sb + ab + 32768u + so, gXl + go);
            }
            CP_COMMIT();
            CP_WAIT1();     // current tile's group complete; prefetch in flight
        } else {
            CP_WAIT0();
        }
        __syncthreads();

        uint32_t abase = sb + ((mt & 1) ? PB_A1 : PB_A0);

        float acc[2][4][4];
#pragma unroll
        for (int i = 0; i < 2; ++i)
#pragma unroll
            for (int j = 0; j < 4; ++j)
#pragma unroll
                for (int q = 0; q < 4; ++q) acc[i][j][q] = 0.0f;

#pragma unroll
        for (int k16 = 0; k16 < 8; ++k16) {
            uint32_t uxa = (uint32_t)(((2 * k16 + ua) ^ l7) << 4);
            uint32_t uxb = (uint32_t)(((2 * k16 + ub) ^ l7) << 4);

            uint32_t aH[2][4], bH[2][4];
#pragma unroll
            for (int mf = 0; mf < 2; ++mf)
                LDMATRIX_X4(aH[mf][0], aH[mf][1], aH[mf][2], aH[mf][3],
                            abase + arel[mf] + uxa);
#pragma unroll
            for (int nf2 = 0; nf2 < 2; ++nf2)
                LDMATRIX_X4(bH[nf2][0], bH[nf2][1], bH[nf2][2], bH[nf2][3],
                            brow[nf2] + uxb);

            // Term 1: Ah * Bh
#pragma unroll
            for (int mf = 0; mf < 2; ++mf)
#pragma unroll
                for (int nf = 0; nf < 4; ++nf)
                    MMA_BF16(acc[mf][nf], aH[mf][0], aH[mf][1], aH[mf][2], aH[mf][3],
                             bH[nf >> 1][(nf & 1) * 2], bH[nf >> 1][(nf & 1) * 2 + 1]);

            // Term 2: Ah * Bl
            {
                uint32_t bL[2][4];
#pragma unroll
                for (int nf2 = 0; nf2 < 2; ++nf2)
                    LDMATRIX_X4(bL[nf2][0], bL[nf2][1], bL[nf2][2], bL[nf2][3],
                                brow[nf2] + 32768u + uxb);
#pragma unroll
                for (int mf = 0; mf < 2; ++mf)
#pragma unroll
                    for (int nf = 0; nf < 4; ++nf)
                        MMA_BF16(acc[mf][nf], aH[mf][0], aH[mf][1], aH[mf][2], aH[mf][3],
                                 bL[nf >> 1][(nf & 1) * 2], bL[nf >> 1][(nf & 1) * 2 + 1]);
            }

            // Term 3: Al * Bh
            {
                uint32_t aL[2][4];
#pragma unroll
                for (int mf = 0; mf < 2; ++mf)
                    LDMATRIX_X4(aL[mf][0], aL[mf][1], aL[mf][2], aL[mf][3],
                                abase + 32768u + arel[mf] + uxa);
#pragma unroll
                for (int mf = 0; mf < 2; ++mf)
#pragma unroll
                    for (int nf = 0; nf < 4; ++nf)
                        MMA_BF16(acc[mf][nf], aL[mf][0], aL[mf][1], aL[mf][2], aL[mf][3],
                                 bH[nf >> 1][(nf & 1) * 2], bH[nf >> 1][(nf & 1) * 2 + 1]);
            }
        }

        // ---- epilogue: write into (B,S,V) layout ----
        int m0 = mt * 128;
#pragma unroll
        for (int mf = 0; mf < 2; ++mf) {
            int rr = m0 + wm * 32 + mf * 16 + (lane >> 2);
#pragma unroll
            for (int half = 0; half < 2; ++half) {
                int m = rr + half * 8;
                float* orow = out + (size_t)(m & 7) * SS * VV + (size_t)(m >> 3) * VV;
#pragma unroll
                for (int nf = 0; nf < 4; ++nf) {
                    int c = cbase + nf * 8;
                    float v0 = acc[mf][nf][half * 2 + 0];
                    float v1 = acc[mf][nf][half * 2 + 1];
                    if (full) {
                        orow[c]     = v0;
                        orow[c + 1] = v1;
                    } else {
                        if (c < VV)     orow[c]     = v0;
                        if (c + 1 < VV) orow[c + 1] = v1;
                    }
                }
            }
        }
        __syncthreads();   // all reads of A buffer done before it is refilled
    }
}

// ---------------------------------------------------------------------------
extern "C" void kernel_launch(void* const* d_in, const int* in_sizes, int n_in,
                              void* d_out, int out_size) {
    const int*   input_ids = (const int*)  d_in[0];
    const float* emb       = (const float*)d_in[1];
    const float* layer_W   = (const float*)d_in[2];
    const float* layer_b   = (const float*)d_in[3];
    const float* layer_Wr  = (const float*)d_in[4];
    const float* layer_Wi  = (const float*)d_in[5];
    const float* out_w     = (const float*)d_in[6];
    float* out = (float*)d_out;

    const int smem_layers = (2 * RES + BB * DD + 2 * BB * NN + 2 * DD * 36) * sizeof(float);
    cudaFuncSetAttribute(k_layers,      cudaFuncAttributeMaxDynamicSharedMemorySize, smem_layers);
    cudaFuncSetAttribute(k_logits_pipe, cudaFuncAttributeMaxDynamicSharedMemorySize, (int)SMEM_PIPE);

    k_tables<<<(RES + 255) / 256, 256>>>();
    k_recur<<<BB, DD>>>(input_ids, emb, out);
    k_split_w<<<(WROWS * 32) / 256, 256>>>(out_w);   // independent of recur/layers
    k_layers<<<SS, 256, smem_layers>>>(layer_W, layer_b, layer_Wr, layer_Wi);
    k_split_x<<<(SS * BB * 32) / 256, 256>>>();

    k_logits_pipe<<<NTILES, 512, SMEM_PIPE>>>(out);
}